// round 9
// baseline (speedup 1.0000x reference)
#include <cuda_runtime.h>
#include <cstdint>

#define NV    64
#define TMAX  2048
#define EDIM  512
#define HDIM  64
#define G3    192   // 3*H

// ---------------- scratch ----------------
__device__ float g_xg[(size_t)NV * TMAX * G3];   // [V][T][192] x_gates (+b_ih)
__device__ float g_hT[NV * HDIM];
__device__ float g_Wt[EDIM * G3];                // W_ih transposed: [e][n]
__device__ float g_hid[64];                      // MLP hidden

// ---------------- helpers ----------------
typedef unsigned long long ull;
__device__ __forceinline__ void ffma2(ull &d, ull a, ull b) {
    asm volatile("fma.rn.f32x2 %0, %1, %2, %0;" : "+l"(d) : "l"(a), "l"(b));
}
__device__ __forceinline__ float hsum2(ull d) {
    unsigned int a, b;
    asm("mov.b64 {%0, %1}, %2;" : "=r"(a), "=r"(b) : "l"(d));
    return __uint_as_float(a) + __uint_as_float(b);
}
__device__ __forceinline__ void unpack2(ull d, float &x, float &y) {
    unsigned int a, b;
    asm("mov.b64 {%0, %1}, %2;" : "=r"(a), "=r"(b) : "l"(d));
    x = __uint_as_float(a); y = __uint_as_float(b);
}
__device__ __forceinline__ void cp_async16(void* dst, const void* src) {
    unsigned int d = (unsigned int)__cvta_generic_to_shared(dst);
    asm volatile("cp.async.ca.shared.global [%0], [%1], 16;" :: "r"(d), "l"(src));
}
__device__ __forceinline__ float tanh_fast(float x) {
    float y;
    asm("tanh.approx.f32 %0, %1;" : "=f"(y) : "f"(x));
    return y;
}
__device__ __forceinline__ float sigmoid_fast(float x) {
    return fmaf(0.5f, tanh_fast(0.5f * x), 0.5f);
}

// =====================================================================
// Kernel 0: transpose W_ih [192,512] -> g_Wt [512,192]
// =====================================================================
__global__ __launch_bounds__(256) void transpose_wih(const float* __restrict__ W_ih)
{
    int idx = blockIdx.x * 256 + threadIdx.x;
    if (idx < EDIM * G3) {
        int e = idx / G3, n = idx - e * G3;
        g_Wt[idx] = W_ih[(size_t)n * EDIM + e];
    }
}

// =====================================================================
// Kernel 1: x_gates GEMM, double-buffered (unchanged).
// Block 64(M) x 192(N) x 32(K), 128 threads, 8x12 f32x2 microtile.
// =====================================================================
extern __shared__ __align__(16) char g_dynsmem[];

__global__ __launch_bounds__(128, 2) void gemm_kernel(
    const float* __restrict__ emb, const int* __restrict__ lengths,
    const float* __restrict__ b_ih)
{
    const int v  = blockIdx.y;
    const int tt = blockIdx.x;
    if (tt * 64 >= lengths[v]) return;

    float2 (*Asd)[32][64] = (float2 (*)[32][64])g_dynsmem;
    float  (*Bs)[32][192] = (float (*)[32][192])(g_dynsmem + 2 * 32 * 64 * sizeof(float2));

    const int tid = threadIdx.x;
    const int tm = tid >> 4;
    const int tn = tid & 15;
    const int ar = tid >> 1;
    const int aq = tid & 1;
    const int kb = tid >> 2;
    const int seg = tid & 3;

    const float* Ag = emb + ((size_t)v * TMAX + (size_t)tt * 64 + ar) * EDIM + aq * 16;
    const float* Bg = g_Wt + (size_t)kb * G3 + seg * 48;

    ull acc[8][6];
#pragma unroll
    for (int i = 0; i < 8; i++)
#pragma unroll
        for (int j = 0; j < 6; j++) acc[i][j] = 0ull;

    float4 aR[4];
#pragma unroll
    for (int i = 0; i < 4; i++) aR[i] = *(const float4*)(Ag + i * 4);
#pragma unroll
    for (int i = 0; i < 12; i++)
        cp_async16(&Bs[0][kb][seg * 48 + i * 4], Bg + i * 4);
    asm volatile("cp.async.commit_group;" ::: "memory");
#pragma unroll
    for (int i = 0; i < 4; i++) {
        Asd[0][aq * 16 + i * 4 + 0][ar] = make_float2(aR[i].x, aR[i].x);
        Asd[0][aq * 16 + i * 4 + 1][ar] = make_float2(aR[i].y, aR[i].y);
        Asd[0][aq * 16 + i * 4 + 2][ar] = make_float2(aR[i].z, aR[i].z);
        Asd[0][aq * 16 + i * 4 + 3][ar] = make_float2(aR[i].w, aR[i].w);
    }
#pragma unroll
    for (int i = 0; i < 4; i++) aR[i] = *(const float4*)(Ag + 32 + i * 4);
    asm volatile("cp.async.wait_group 0;" ::: "memory");
    __syncthreads();

    for (int it = 0; it < 16; it++) {
        const int cur = it & 1, nxt = cur ^ 1;
        if (it < 15) {
            const float* bsrc = Bg + (size_t)(it + 1) * 32 * G3;
#pragma unroll
            for (int i = 0; i < 12; i++)
                cp_async16(&Bs[nxt][kb][seg * 48 + i * 4], bsrc + i * 4);
            asm volatile("cp.async.commit_group;" ::: "memory");
#pragma unroll
            for (int i = 0; i < 4; i++) {
                Asd[nxt][aq * 16 + i * 4 + 0][ar] = make_float2(aR[i].x, aR[i].x);
                Asd[nxt][aq * 16 + i * 4 + 1][ar] = make_float2(aR[i].y, aR[i].y);
                Asd[nxt][aq * 16 + i * 4 + 2][ar] = make_float2(aR[i].z, aR[i].z);
                Asd[nxt][aq * 16 + i * 4 + 3][ar] = make_float2(aR[i].w, aR[i].w);
            }
            if (it < 14) {
#pragma unroll
                for (int i = 0; i < 4; i++)
                    aR[i] = *(const float4*)(Ag + (it + 2) * 32 + i * 4);
            }
        }
#pragma unroll 4
        for (int kk = 0; kk < 32; kk++) {
            ull a8[8];
            const ull* ap = (const ull*)&Asd[cur][kk][tm * 8];
#pragma unroll
            for (int i = 0; i < 8; i++) a8[i] = ap[i];
            ull b6[6];
            const ull* bp = (const ull*)&Bs[cur][kk][tn * 12];
#pragma unroll
            for (int j = 0; j < 6; j++) b6[j] = bp[j];
#pragma unroll
            for (int i = 0; i < 8; i++)
#pragma unroll
                for (int j = 0; j < 6; j++) ffma2(acc[i][j], a8[i], b6[j]);
        }
        if (it < 15) {
            asm volatile("cp.async.wait_group 0;" ::: "memory");
            __syncthreads();
        }
    }

    float bias[12];
    *(float4*)&bias[0] = *(const float4*)(b_ih + tn * 12 + 0);
    *(float4*)&bias[4] = *(const float4*)(b_ih + tn * 12 + 4);
    *(float4*)&bias[8] = *(const float4*)(b_ih + tn * 12 + 8);
#pragma unroll
    for (int i = 0; i < 8; i++) {
        size_t row = (size_t)v * TMAX + (size_t)tt * 64 + tm * 8 + i;
        float* outp = g_xg + row * G3 + tn * 12;
        float o[12];
#pragma unroll
        for (int j = 0; j < 6; j++) {
            float x, y; unpack2(acc[i][j], x, y);
            o[2 * j]     = x + bias[2 * j];
            o[2 * j + 1] = y + bias[2 * j + 1];
        }
        *(float4*)(outp + 0) = make_float4(o[0], o[1], o[2], o[3]);
        *(float4*)(outp + 4) = make_float4(o[4], o[5], o[6], o[7]);
        *(float4*)(outp + 8) = make_float4(o[8], o[9], o[10], o[11]);
    }
}

// =====================================================================
// Kernel 2: GRU scan. 128 threads = (j 0..63) x (half 0..1), lane pairs.
// h stored TWICE in one manually laid-out buffer so the two 32-float
// segments read by even/odd lanes occupy DISJOINT banks:
//   copy A (h[0..64))  at hbuf[p][0]   -> chunk-i banks {8p+4i..+3}
//   copy B (h[32..64)) at hbuf[p][68]  -> chunk-i banks {8p+4+4i..+3}
// (row stride 104 floats; 68 mod 32 = 4 -> disjoint, placement-independent)
// h loaded as 8x LDS.128 (longlong2), conflict-free broadcast.
// cp.async ring + MUFU.TANH unchanged.
// =====================================================================
__global__ __launch_bounds__(128) void scan_kernel(
    const int* __restrict__ lengths, const float* __restrict__ W_hh,
    const float* __restrict__ b_hh)
{
    const int v   = blockIdx.x;
    const int len = lengths[v];
    const int tid = threadIdx.x;
    const int j    = tid >> 1;
    const int half = tid & 1;

    __shared__ __align__(16) float hbuf[2][104];
    __shared__ __align__(16) float sh_xg[4][G3];

    ull wr[16], wz[16], wn[16];
    {
        const ull* pr = (const ull*)(W_hh + (size_t)(j)       * HDIM + half * 32);
        const ull* pz = (const ull*)(W_hh + (size_t)(64 + j)  * HDIM + half * 32);
        const ull* pn = (const ull*)(W_hh + (size_t)(128 + j) * HDIM + half * 32);
#pragma unroll
        for (int i = 0; i < 16; i++) { wr[i] = pr[i]; wz[i] = pz[i]; wn[i] = pn[i]; }
    }
    const float br = b_hh[j], bz = b_hh[64 + j], bn = b_hh[128 + j];
    float myh = 0.f;
    if (tid < 64) hbuf[0][tid] = 0.f;
    if (tid < 32) hbuf[0][68 + tid] = 0.f;

    const float* xgbase = g_xg + (size_t)v * TMAX * G3;

    // prefill 3 buffers (data 0,1,2), one commit group each
#pragma unroll
    for (int i = 0; i < 3; i++) {
        if (tid < 48)
            cp_async16(&sh_xg[i][tid * 4], xgbase + (size_t)i * G3 + tid * 4);
        asm volatile("cp.async.commit_group;" ::: "memory");
    }
    asm volatile("cp.async.wait_group 2;" ::: "memory");
    __syncthreads();

    // my 32-float h segment: copy A for half==0, copy B for half==1
    const int hoff = half * 68;

    for (int t = 0; t < len; t++) {
        const int buf = t & 3;
        float xr = sh_xg[buf][j];
        float xz = sh_xg[buf][64 + j];
        float xn = sh_xg[buf][128 + j];

        // conflict-free LDS.128 loads of my h segment
        const longlong2* hp = (const longlong2*)(&hbuf[t & 1][hoff]);
        ull h8[16];
#pragma unroll
        for (int i = 0; i < 8; i++) {
            longlong2 v2 = hp[i];
            h8[2 * i]     = (ull)v2.x;
            h8[2 * i + 1] = (ull)v2.y;
        }

        ull a0 = 0ull, a1 = 0ull;
#pragma unroll
        for (int i = 0; i < 16; i += 2) { ffma2(a0, wr[i], h8[i]); ffma2(a1, wr[i + 1], h8[i + 1]); }
        float sr = hsum2(a0) + hsum2(a1);
        sr += __shfl_xor_sync(0xffffffffu, sr, 1);   // issues early; z-fma hides it

        ull c0 = 0ull, c1 = 0ull;
#pragma unroll
        for (int i = 0; i < 16; i += 2) { ffma2(c0, wz[i], h8[i]); ffma2(c1, wz[i + 1], h8[i + 1]); }
        float sz = hsum2(c0) + hsum2(c1);
        sz += __shfl_xor_sync(0xffffffffu, sz, 1);

        float rr = sigmoid_fast(xr + sr + br);       // MUFU.TANH, hides under n-fma

        ull e0 = 0ull, e1 = 0ull;
#pragma unroll
        for (int i = 0; i < 16; i += 2) { ffma2(e0, wn[i], h8[i]); ffma2(e1, wn[i + 1], h8[i + 1]); }
        float sn = hsum2(e0) + hsum2(e1);
        sn += __shfl_xor_sync(0xffffffffu, sn, 1);

        float zz = sigmoid_fast(xz + sz + bz);
        float pre = xn + rr * (sn + bn);
        float nn = tanh_fast(pre);
        myh = nn + zz * (myh - nn);

        // write both copies of h for next step
        const int p = (t + 1) & 1;
        if (half == 0)      hbuf[p][j] = myh;
        else if (j >= 32)   hbuf[p][68 + (j - 32)] = myh;

        // refill: data t+3 into buffer (t+3)&3 (step-(t-1) reads barrier-separated)
        {
            int src = t + 3; if (src > TMAX - 1) src = TMAX - 1;
            if (tid < 48)
                cp_async16(&sh_xg[(t + 3) & 3][tid * 4],
                           xgbase + (size_t)src * G3 + tid * 4);
            asm volatile("cp.async.commit_group;" ::: "memory");
        }
        // my groups for data t+1 done, then barrier -> visible to all. ONE barrier/step.
        asm volatile("cp.async.wait_group 2;" ::: "memory");
        __syncthreads();
    }
    asm volatile("cp.async.wait_group 0;" ::: "memory");

    if (half == 0) g_hT[v * HDIM + j] = myh;
}

// =====================================================================
// Kernel 3a: MLP layer 1 — 64 blocks, one hidden unit each.
// =====================================================================
__global__ __launch_bounds__(128) void mlp1_kernel(
    const float* __restrict__ W1, const float* __restrict__ b1)
{
    const int i = blockIdx.x;
    const int tid = threadIdx.x;
    const int warp = tid >> 5, lane = tid & 31;
    __shared__ float red[4];

    const float* wrow = W1 + (size_t)i * (NV * HDIM);
    float s = 0.f;
#pragma unroll
    for (int it = 0; it < 8; it++) {
        int k = (it * 128 + tid) * 4;
        float4 wv = *(const float4*)(wrow + k);
        float4 hv = *(const float4*)(g_hT + k);
        s += wv.x * hv.x + wv.y * hv.y + wv.z * hv.z + wv.w * hv.w;
    }
#pragma unroll
    for (int off = 16; off; off >>= 1) s += __shfl_xor_sync(0xffffffffu, s, off);
    if (lane == 0) red[warp] = s;
    __syncthreads();
    if (tid == 0)
        g_hid[i] = fmaxf(red[0] + red[1] + red[2] + red[3] + b1[i], 0.f);
}

// =====================================================================
// Kernel 3b: MLP layer 2 — one warp.
// =====================================================================
__global__ __launch_bounds__(32) void mlp2_kernel(
    const float* __restrict__ W2, const float* __restrict__ b2,
    float* __restrict__ out)
{
    const int lane = threadIdx.x;
    float s = g_hid[lane] * W2[lane] + g_hid[lane + 32] * W2[lane + 32];
#pragma unroll
    for (int off = 16; off; off >>= 1) s += __shfl_xor_sync(0xffffffffu, s, off);
    if (lane == 0) out[0] = s + b2[0];
}

// =====================================================================
extern "C" void kernel_launch(void* const* d_in, const int* in_sizes, int n_in,
                              void* d_out, int out_size)
{
    const float* emb     = (const float*)d_in[0];
    const int*   lengths = (const int*)  d_in[1];
    const float* W_ih    = (const float*)d_in[2];
    const float* W_hh    = (const float*)d_in[3];
    const float* b_ih    = (const float*)d_in[4];
    const float* b_hh    = (const float*)d_in[5];
    const float* W1      = (const float*)d_in[6];
    const float* b1      = (const float*)d_in[7];
    const float* W2      = (const float*)d_in[8];
    const float* b2      = (const float*)d_in[9];

    static int smem_set = 0;
    const int GEMM_SMEM = 2 * 32 * 64 * (int)sizeof(float2) + 2 * 32 * 192 * (int)sizeof(float);
    if (!smem_set) {
        cudaFuncSetAttribute(gemm_kernel, cudaFuncAttributeMaxDynamicSharedMemorySize, GEMM_SMEM);
        smem_set = 1;
    }

    transpose_wih<<<(EDIM * G3 + 255) / 256, 256>>>(W_ih);
    dim3 ggrid(TMAX / 64, NV);
    gemm_kernel<<<ggrid, 128, GEMM_SMEM>>>(emb, lengths, b_ih);
    scan_kernel<<<NV, 128>>>(lengths, W_hh, b_hh);
    mlp1_kernel<<<64, 128>>>(W1, b1);
    mlp2_kernel<<<1, 32>>>(W2, b2, (float*)d_out);
}

// round 10
// speedup vs baseline: 1.3224x; 1.3224x over previous
#include <cuda_runtime.h>
#include <cstdint>

#define NV    64
#define TMAX  2048
#define EDIM  512
#define HDIM  64
#define G3    192   // 3*H
#define NCHUNK (TMAX / 64)   // 32

// ---------------- scratch ----------------
__device__ float g_xg[(size_t)NV * TMAX * G3];   // [V][T][192] x_gates (+b_ih)
__device__ float g_hT[NV * HDIM];
__device__ float g_Wt[EDIM * G3];                // W_ih transposed: [e][n]
__device__ float g_hid[64];                      // MLP hidden
__device__ volatile unsigned g_flag[NV * NCHUNK];// producer->consumer ready flags

// ---------------- helpers ----------------
typedef unsigned long long ull;
__device__ __forceinline__ void ffma2(ull &d, ull a, ull b) {
    asm volatile("fma.rn.f32x2 %0, %1, %2, %0;" : "+l"(d) : "l"(a), "l"(b));
}
__device__ __forceinline__ float hsum2(ull d) {
    unsigned int a, b;
    asm("mov.b64 {%0, %1}, %2;" : "=r"(a), "=r"(b) : "l"(d));
    return __uint_as_float(a) + __uint_as_float(b);
}
__device__ __forceinline__ void unpack2(ull d, float &x, float &y) {
    unsigned int a, b;
    asm("mov.b64 {%0, %1}, %2;" : "=r"(a), "=r"(b) : "l"(d));
    x = __uint_as_float(a); y = __uint_as_float(b);
}
__device__ __forceinline__ void cp_async16(void* dst, const void* src) {
    unsigned int d = (unsigned int)__cvta_generic_to_shared(dst);
    asm volatile("cp.async.ca.shared.global [%0], [%1], 16;" :: "r"(d), "l"(src));
}
__device__ __forceinline__ float tanh_fast(float x) {
    float y;
    asm("tanh.approx.f32 %0, %1;" : "=f"(y) : "f"(x));
    return y;
}
__device__ __forceinline__ float sigmoid_fast(float x) {
    return fmaf(0.5f, tanh_fast(0.5f * x), 0.5f);
}

// =====================================================================
// Kernel 0: transpose W_ih [192,512] -> g_Wt [512,192]; zero flags.
// =====================================================================
__global__ __launch_bounds__(256) void transpose_wih(const float* __restrict__ W_ih)
{
    int idx = blockIdx.x * 256 + threadIdx.x;
    if (idx < EDIM * G3) {
        int e = idx / G3, n = idx - e * G3;
        g_Wt[idx] = W_ih[(size_t)n * EDIM + e];
    }
    if (blockIdx.x == 0) {
        for (int i = threadIdx.x; i < NV * NCHUNK; i += 256) g_flag[i] = 0u;
    }
}

// =====================================================================
// FUSED kernel: bids 0..63 = GRU scan consumers (one per variable),
// bids 64..2111 = x_gates GEMM producers (chunk-major, v-fast order).
// =====================================================================
extern __shared__ __align__(16) char g_dynsmem[];

// ---- producer: 64(M) x 192(N) x 32(K) double-buffered GEMM tile ----
__device__ void gemm_role(int v, int tt,
                          const float* __restrict__ emb,
                          const int* __restrict__ lengths,
                          const float* __restrict__ b_ih)
{
    const int tid = threadIdx.x;
    const int len = lengths[v];
    if (tt * 64 >= len) {           // tile never consumed (h frozen past len)
        if (tid == 0) g_flag[v * NCHUNK + tt] = 1u;   // set anyway: no waiter, no harm
        return;
    }

    float2 (*Asd)[32][64] = (float2 (*)[32][64])g_dynsmem;
    float  (*Bs)[32][192] = (float (*)[32][192])(g_dynsmem + 2 * 32 * 64 * sizeof(float2));

    const int tm = tid >> 4;
    const int tn = tid & 15;
    const int ar = tid >> 1;
    const int aq = tid & 1;
    const int kb = tid >> 2;
    const int seg = tid & 3;

    const float* Ag = emb + ((size_t)v * TMAX + (size_t)tt * 64 + ar) * EDIM + aq * 16;
    const float* Bg = g_Wt + (size_t)kb * G3 + seg * 48;

    ull acc[8][6];
#pragma unroll
    for (int i = 0; i < 8; i++)
#pragma unroll
        for (int j = 0; j < 6; j++) acc[i][j] = 0ull;

    float4 aR[4];
#pragma unroll
    for (int i = 0; i < 4; i++) aR[i] = *(const float4*)(Ag + i * 4);
#pragma unroll
    for (int i = 0; i < 12; i++)
        cp_async16(&Bs[0][kb][seg * 48 + i * 4], Bg + i * 4);
    asm volatile("cp.async.commit_group;" ::: "memory");
#pragma unroll
    for (int i = 0; i < 4; i++) {
        Asd[0][aq * 16 + i * 4 + 0][ar] = make_float2(aR[i].x, aR[i].x);
        Asd[0][aq * 16 + i * 4 + 1][ar] = make_float2(aR[i].y, aR[i].y);
        Asd[0][aq * 16 + i * 4 + 2][ar] = make_float2(aR[i].z, aR[i].z);
        Asd[0][aq * 16 + i * 4 + 3][ar] = make_float2(aR[i].w, aR[i].w);
    }
#pragma unroll
    for (int i = 0; i < 4; i++) aR[i] = *(const float4*)(Ag + 32 + i * 4);
    asm volatile("cp.async.wait_group 0;" ::: "memory");
    __syncthreads();

    for (int it = 0; it < 16; it++) {
        const int cur = it & 1, nxt = cur ^ 1;
        if (it < 15) {
            const float* bsrc = Bg + (size_t)(it + 1) * 32 * G3;
#pragma unroll
            for (int i = 0; i < 12; i++)
                cp_async16(&Bs[nxt][kb][seg * 48 + i * 4], bsrc + i * 4);
            asm volatile("cp.async.commit_group;" ::: "memory");
#pragma unroll
            for (int i = 0; i < 4; i++) {
                Asd[nxt][aq * 16 + i * 4 + 0][ar] = make_float2(aR[i].x, aR[i].x);
                Asd[nxt][aq * 16 + i * 4 + 1][ar] = make_float2(aR[i].y, aR[i].y);
                Asd[nxt][aq * 16 + i * 4 + 2][ar] = make_float2(aR[i].z, aR[i].z);
                Asd[nxt][aq * 16 + i * 4 + 3][ar] = make_float2(aR[i].w, aR[i].w);
            }
            if (it < 14) {
#pragma unroll
                for (int i = 0; i < 4; i++)
                    aR[i] = *(const float4*)(Ag + (it + 2) * 32 + i * 4);
            }
        }
#pragma unroll 4
        for (int kk = 0; kk < 32; kk++) {
            ull a8[8];
            const ull* ap = (const ull*)&Asd[cur][kk][tm * 8];
#pragma unroll
            for (int i = 0; i < 8; i++) a8[i] = ap[i];
            ull b6[6];
            const ull* bp = (const ull*)&Bs[cur][kk][tn * 12];
#pragma unroll
            for (int j = 0; j < 6; j++) b6[j] = bp[j];
#pragma unroll
            for (int i = 0; i < 8; i++)
#pragma unroll
                for (int j = 0; j < 6; j++) ffma2(acc[i][j], a8[i], b6[j]);
        }
        if (it < 15) {
            asm volatile("cp.async.wait_group 0;" ::: "memory");
            __syncthreads();
        }
    }

    float bias[12];
    *(float4*)&bias[0] = *(const float4*)(b_ih + tn * 12 + 0);
    *(float4*)&bias[4] = *(const float4*)(b_ih + tn * 12 + 4);
    *(float4*)&bias[8] = *(const float4*)(b_ih + tn * 12 + 8);
#pragma unroll
    for (int i = 0; i < 8; i++) {
        size_t row = (size_t)v * TMAX + (size_t)tt * 64 + tm * 8 + i;
        float* outp = g_xg + row * G3 + tn * 12;
        float o[12];
#pragma unroll
        for (int j = 0; j < 6; j++) {
            float x, y; unpack2(acc[i][j], x, y);
            o[2 * j]     = x + bias[2 * j];
            o[2 * j + 1] = y + bias[2 * j + 1];
        }
        *(float4*)(outp + 0) = make_float4(o[0], o[1], o[2], o[3]);
        *(float4*)(outp + 4) = make_float4(o[4], o[5], o[6], o[7]);
        *(float4*)(outp + 8) = make_float4(o[8], o[9], o[10], o[11]);
    }

    // publish this (v, chunk): all threads fence their STGs, then leader flags.
    __threadfence();
    __syncthreads();
    if (tid == 0) g_flag[v * NCHUNK + tt] = 1u;
}

// ---- consumer: round-7 scan + chunk gating on the prefetch ----
__device__ void scan_role(int v,
                          const int* __restrict__ lengths,
                          const float* __restrict__ W_hh,
                          const float* __restrict__ b_hh)
{
    const int len = lengths[v];
    const int tid = threadIdx.x;
    const int j    = tid >> 1;
    const int half = tid & 1;

    float (*sh_h)[HDIM] = (float (*)[HDIM])g_dynsmem;                 // [2][64]
    float (*sh_xg)[G3]  = (float (*)[G3])(g_dynsmem + 2 * HDIM * 4);  // [4][192]

    ull wr[16], wz[16], wn[16];
    {
        const ull* pr = (const ull*)(W_hh + (size_t)(j)       * HDIM + half * 32);
        const ull* pz = (const ull*)(W_hh + (size_t)(64 + j)  * HDIM + half * 32);
        const ull* pn = (const ull*)(W_hh + (size_t)(128 + j) * HDIM + half * 32);
#pragma unroll
        for (int i = 0; i < 16; i++) { wr[i] = pr[i]; wz[i] = pz[i]; wn[i] = pn[i]; }
    }
    const float br = b_hh[j], bz = b_hh[64 + j], bn = b_hh[128 + j];
    float myh = 0.f;
    if (tid < HDIM) sh_h[0][tid] = 0.f;

    const float* xgbase = g_xg + (size_t)v * TMAX * G3;
    int confirmed = -1;   // highest chunk known ready (per copying thread)

    if (len > 0) {
        // wait for chunk 0, then prefill 3 buffers (rows clamped to len-1)
        if (tid < 48) {
            while (g_flag[v * NCHUNK + 0] == 0u) __nanosleep(64);
            __threadfence();
            confirmed = 0;
        }
#pragma unroll
        for (int i = 0; i < 3; i++) {
            int row = i; if (row > len - 1) row = len - 1;
            if (tid < 48)
                cp_async16(&sh_xg[i][tid * 4], xgbase + (size_t)row * G3 + tid * 4);
            asm volatile("cp.async.commit_group;" ::: "memory");
        }
        asm volatile("cp.async.wait_group 2;" ::: "memory");
    }
    __syncthreads();

    for (int t = 0; t < len; t++) {
        const int buf = t & 3;
        float xr = sh_xg[buf][j];
        float xz = sh_xg[buf][64 + j];
        float xn = sh_xg[buf][128 + j];

        const ull* hp = (const ull*)(&sh_h[t & 1][half * 32]);
        ull h8[16];
#pragma unroll
        for (int i = 0; i < 16; i++) h8[i] = hp[i];

        ull a0 = 0ull, a1 = 0ull;
#pragma unroll
        for (int i = 0; i < 16; i += 2) { ffma2(a0, wr[i], h8[i]); ffma2(a1, wr[i + 1], h8[i + 1]); }
        float sr = hsum2(a0) + hsum2(a1);
        sr += __shfl_xor_sync(0xffffffffu, sr, 1);

        ull c0 = 0ull, c1 = 0ull;
#pragma unroll
        for (int i = 0; i < 16; i += 2) { ffma2(c0, wz[i], h8[i]); ffma2(c1, wz[i + 1], h8[i + 1]); }
        float sz = hsum2(c0) + hsum2(c1);
        sz += __shfl_xor_sync(0xffffffffu, sz, 1);

        float rr = sigmoid_fast(xr + sr + br);

        ull e0 = 0ull, e1 = 0ull;
#pragma unroll
        for (int i = 0; i < 16; i += 2) { ffma2(e0, wn[i], h8[i]); ffma2(e1, wn[i + 1], h8[i + 1]); }
        float sn = hsum2(e0) + hsum2(e1);
        sn += __shfl_xor_sync(0xffffffffu, sn, 1);

        float zz = sigmoid_fast(xz + sz + bz);
        float pre = xn + rr * (sn + bn);
        float nn = tanh_fast(pre);
        myh = nn + zz * (myh - nn);
        if (half == 0) sh_h[(t + 1) & 1][j] = myh;

        // refill data src=min(t+3,len-1): gate on producer flag at chunk crossings
        {
            int src = t + 3; if (src > len - 1) src = len - 1;
            if (tid < 48) {
                int ch = src >> 6;
                if (ch > confirmed) {
                    while (g_flag[v * NCHUNK + ch] == 0u) __nanosleep(64);
                    __threadfence();
                    confirmed = ch;
                }
                cp_async16(&sh_xg[(t + 3) & 3][tid * 4],
                           xgbase + (size_t)src * G3 + tid * 4);
            }
            asm volatile("cp.async.commit_group;" ::: "memory");
        }
        asm volatile("cp.async.wait_group 2;" ::: "memory");
        __syncthreads();
    }
    asm volatile("cp.async.wait_group 0;" ::: "memory");

    if (half == 0) g_hT[v * HDIM + j] = myh;
}

__global__ __launch_bounds__(128, 2) void fused_kernel(
    const float* __restrict__ emb, const int* __restrict__ lengths,
    const float* __restrict__ b_ih, const float* __restrict__ W_hh,
    const float* __restrict__ b_hh)
{
    if (blockIdx.x < NV) {
        scan_role(blockIdx.x, lengths, W_hh, b_hh);
    } else {
        // chunk-major, v-fast: first 64 gemm CTAs = chunk 0 of every variable
        int idx = blockIdx.x - NV;
        gemm_role(idx & 63, idx >> 6, emb, lengths, b_ih);
    }
}

// =====================================================================
// MLP head (unchanged).
// =====================================================================
__global__ __launch_bounds__(128) void mlp1_kernel(
    const float* __restrict__ W1, const float* __restrict__ b1)
{
    const int i = blockIdx.x;
    const int tid = threadIdx.x;
    const int warp = tid >> 5, lane = tid & 31;
    __shared__ float red[4];

    const float* wrow = W1 + (size_t)i * (NV * HDIM);
    float s = 0.f;
#pragma unroll
    for (int it = 0; it < 8; it++) {
        int k = (it * 128 + tid) * 4;
        float4 wv = *(const float4*)(wrow + k);
        float4 hv = *(const float4*)(g_hT + k);
        s += wv.x * hv.x + wv.y * hv.y + wv.z * hv.z + wv.w * hv.w;
    }
#pragma unroll
    for (int off = 16; off; off >>= 1) s += __shfl_xor_sync(0xffffffffu, s, off);
    if (lane == 0) red[warp] = s;
    __syncthreads();
    if (tid == 0)
        g_hid[i] = fmaxf(red[0] + red[1] + red[2] + red[3] + b1[i], 0.f);
}

__global__ __launch_bounds__(32) void mlp2_kernel(
    const float* __restrict__ W2, const float* __restrict__ b2,
    float* __restrict__ out)
{
    const int lane = threadIdx.x;
    float s = g_hid[lane] * W2[lane] + g_hid[lane + 32] * W2[lane + 32];
#pragma unroll
    for (int off = 16; off; off >>= 1) s += __shfl_xor_sync(0xffffffffu, s, off);
    if (lane == 0) out[0] = s + b2[0];
}

// =====================================================================
extern "C" void kernel_launch(void* const* d_in, const int* in_sizes, int n_in,
                              void* d_out, int out_size)
{
    const float* emb     = (const float*)d_in[0];
    const int*   lengths = (const int*)  d_in[1];
    const float* W_ih    = (const float*)d_in[2];
    const float* W_hh    = (const float*)d_in[3];
    const float* b_ih    = (const float*)d_in[4];
    const float* b_hh    = (const float*)d_in[5];
    const float* W1      = (const float*)d_in[6];
    const float* b1      = (const float*)d_in[7];
    const float* W2      = (const float*)d_in[8];
    const float* b2      = (const float*)d_in[9];

    static int smem_set = 0;
    const int FUSED_SMEM = 2 * 32 * 64 * (int)sizeof(float2) + 2 * 32 * 192 * (int)sizeof(float);
    if (!smem_set) {
        cudaFuncSetAttribute(fused_kernel, cudaFuncAttributeMaxDynamicSharedMemorySize, FUSED_SMEM);
        smem_set = 1;
    }

    transpose_wih<<<(EDIM * G3 + 255) / 256, 256>>>(W_ih);
    fused_kernel<<<NV + NV * (TMAX / 64), 128, FUSED_SMEM>>>(emb, lengths, b_ih, W_hh, b_hh);
    mlp1_kernel<<<64, 128>>>(W1, b1);
    mlp2_kernel<<<1, 32>>>(W2, b2, (float*)d_out);
}